// round 9
// baseline (speedup 1.0000x reference)
#include <cuda_runtime.h>

#define NB     16
#define NP     65536
#define NPTS   (NB * NP)                            // 1048576 points
#define RAD_N  5
#define AZI_N  30
#define ELE_N  15
#define KSL    (ELE_N - 1)                          // 14 ele pair-slots
#define PLANE_SLOTS (AZI_N * KSL)                   // 420 slots per (b,r) plane
#define PLANE_OUTS  (AZI_N * ELE_N)                 // 450 out bins per plane
#define NPLANE (NB * RAD_N)                         // 80 planes
#define NSLOT  (NPLANE * PLANE_SLOTS)               // 33600 float4 2x2-slots

#define NBLK   888                                  // 148 SMs * 6 blocks
#define NTHR   256
#define NT     (NBLK * NTHR)                        // 227328 threads
#define NGRP2  (NPTS / 2)                           // 524288 2-point groups

// 2x2 pair-slot histogram: slot[b][r][a][k] (a circular, k=0..13) holds
// contributions to bins (a,k),(a,k+1),(a+1%30,k),(a+1%30,k+1) in (.x,.y,.z,.w).
// INVARIANT: all-zero at kernel entry (zero-init at load; fold phase re-zeros).
__device__ float4 g_slots[NSLOT];

// Grid barrier: g_bar_gen monotone across replays; g_bar_count self-resets.
__device__ unsigned g_bar_count = 0;
__device__ unsigned g_bar_gen   = 0;

__device__ __forceinline__ void red_add4(float4* a, float x, float y, float z, float w) {
    asm volatile("red.global.add.v4.f32 [%0], {%1, %2, %3, %4};"
                 :: "l"(a), "f"(x), "f"(y), "f"(z), "f"(w) : "memory");
}

__device__ __forceinline__ void scatter_point(float x, float y, float z, int b) {
    float r = sqrtf(x * x + y * y + z * z);
    if (r > 2.0f) return;   // reference culls r > DES_R

    float azi = atan2f(y, x);
    if (azi < 0.f) azi += 6.28318530717958647692f;
    float ce  = fminf(fmaxf(z / fmaxf(r, 1e-12f), -1.f), 1.f);
    float ele = acosf(ce);

    // radial pair: closed form of ref's half-bin boundary clamps
    float vr = r * 2.5f - 0.5f;
    int jr; float wr0, wr1;
    if (vr < 0.f)        { jr = 0; wr0 = 1.f; wr1 = 0.f; }
    else if (vr >= 4.f)  { jr = 3; wr0 = 0.f; wr1 = 5.f - vr; }
    else { jr = (int)vr; float f = vr - (float)jr; wr0 = 1.f - f; wr1 = f; }

    // azimuth pair: circular; slot sa covers bins (sa, sa+1 mod 30)
    float va = azi * (float)(AZI_N / 6.283185307179586) - 0.5f;
    float fj = floorf(va);
    int   j  = (int)fj;                 // in [-1, 29]
    float fa = va - fj;
    int sa = (j < 0) ? (AZI_N - 1) : j;
    float wa0 = 1.f - fa, wa1 = fa;

    // elevation pair: both-end half-bin clamps
    float ve = ele * (float)(ELE_N / 3.141592653589793) - 0.5f;
    int ke; float we0, we1;
    if (ve < 0.f)         { ke = 0;  we0 = 1.f; we1 = 0.f; }
    else if (ve >= 14.f)  { ke = 13; we0 = 0.f; we1 = 1.f; }
    else { ke = (int)ve; float f = ve - (float)ke; we0 = 1.f - f; we1 = f; }

    float p00 = wa0 * we0, p01 = wa0 * we1;
    float p10 = wa1 * we0, p11 = wa1 * we1;

    int s0 = ((b * RAD_N + jr) * AZI_N + sa) * KSL + ke;
    if (wr0 != 0.f)
        red_add4(&g_slots[s0], wr0 * p00, wr0 * p01, wr0 * p10, wr0 * p11);
    if (wr1 != 0.f)
        red_add4(&g_slots[s0 + PLANE_SLOTS], wr1 * p00, wr1 * p01, wr1 * p10, wr1 * p11);
}

__global__ void __launch_bounds__(NTHR, 6) fused_kernel(const float* __restrict__ pts,
                                                        float* __restrict__ out) {
    int gtid = blockIdx.x * NTHR + threadIdx.x;

    // ---- Phase 1: scatter, 2 points per iteration via 3x float2 loads ----
    const float2* p2 = (const float2*)pts;
    for (int g = gtid; g < NGRP2; g += NT) {
        float2 v0 = __ldg(p2 + 3 * g);
        float2 v1 = __ldg(p2 + 3 * g + 1);
        float2 v2 = __ldg(p2 + 3 * g + 2);
        int b = (2 * g) >> 16;            // both points share batch (NP even)
        scatter_point(v0.x, v0.y, v1.x, b);
        scatter_point(v1.y, v2.x, v2.y, b);
    }

    // ---- Grid barrier (all 888 blocks co-resident by launch_bounds) ----
    __threadfence();          // make this block's red ops visible
    __syncthreads();
    if (threadIdx.x == 0) {
        unsigned old = atomicAdd(&g_bar_gen, 0u);
        unsigned t   = atomicAdd(&g_bar_count, 1u);
        if (t == NBLK - 1) {
            atomicExch(&g_bar_count, 0u);
            __threadfence();
            atomicAdd(&g_bar_gen, 1u);
        } else {
            while (atomicAdd(&g_bar_gen, 0u) == old) { __nanosleep(64); }
            __threadfence();
        }
    }
    __syncthreads();

    // ---- Phase 2: blocks 0..79 fold one (b,r) plane each, re-zeroing slots ----
    if (blockIdx.x < NPLANE) {
        __shared__ float4 s[PLANE_SLOTS];
        int plane = blockIdx.x;
        int tid = threadIdx.x;

        float4* gp = g_slots + plane * PLANE_SLOTS;
        for (int i = tid; i < PLANE_SLOTS; i += NTHR) {
            float4 v = __ldcg(&gp[i]);    // L2-bypass of L1: red updates L2 only
            s[i] = v;
            __stcg(&gp[i], make_float4(0.f, 0.f, 0.f, 0.f));  // restore invariant
        }
        __syncthreads();

        for (int i = tid; i < PLANE_OUTS; i += NTHR) {
            int e   = i % ELE_N;
            int a   = i / ELE_N;
            int am1 = (a == 0) ? (AZI_N - 1) : (a - 1);

            float v = 0.f;
            if (e < KSL) {
                v += s[a   * KSL + e].x;
                v += s[am1 * KSL + e].z;
            }
            if (e > 0) {
                v += s[a   * KSL + e - 1].y;
                v += s[am1 * KSL + e - 1].w;
            }
            out[plane * PLANE_OUTS + i] = v;
        }
    }
}

extern "C" void kernel_launch(void* const* d_in, const int* in_sizes, int n_in,
                              void* d_out, int out_size) {
    const float* pts = (const float*)d_in[0];
    float* out = (float*)d_out;
    fused_kernel<<<NBLK, NTHR>>>(pts, out);
}

// round 10
// speedup vs baseline: 1.0932x; 1.0932x over previous
#include <cuda_runtime.h>

#define NB     16
#define NP     65536
#define NPTS   (NB * NP)                            // 1048576 points
#define RAD_N  5
#define AZI_N  30
#define ELE_N  15
#define KSL    (ELE_N - 1)                          // 14 ele pair-slots
#define PLANE_SLOTS (AZI_N * KSL)                   // 420 slots per (b,r) plane
#define PLANE_OUTS  (AZI_N * ELE_N)                 // 450 out bins per plane
#define NPLANE (NB * RAD_N)                         // 80 planes
#define NSLOT  (NPLANE * PLANE_SLOTS)               // 33600 float4 2x2-slots

#define NBLK   888                                  // 148 SMs * 6 blocks
#define NTHR   256
#define NT     (NBLK * NTHR)                        // 227328 threads
#define NGRP2  (NPTS / 2)                           // 524288 2-point groups

// 2x2 pair-slot histogram: slot[b][r][a][k] (a circular, k=0..13) holds
// contributions to bins (a,k),(a,k+1),(a+1%30,k),(a+1%30,k+1) in (.x,.y,.z,.w).
// INVARIANT: all-zero at kernel entry (zero-init at load; fold phase re-zeros).
__device__ float4 g_slots[NSLOT];

// Grid barrier: g_bar_gen monotone across replays; g_bar_count self-resets.
__device__ unsigned g_bar_count = 0;
__device__ unsigned g_bar_gen   = 0;

__device__ __forceinline__ void red_add4(float4* a, float x, float y, float z, float w) {
    asm volatile("red.global.add.v4.f32 [%0], {%1, %2, %3, %4};"
                 :: "l"(a), "f"(x), "f"(y), "f"(z), "f"(w) : "memory");
}

__device__ __forceinline__ void scatter_point(float x, float y, float z, int b) {
    float r = sqrtf(x * x + y * y + z * z);
    if (r > 2.0f) return;   // reference culls r > DES_R

    float azi = atan2f(y, x);
    if (azi < 0.f) azi += 6.28318530717958647692f;
    float ce  = fminf(fmaxf(z / fmaxf(r, 1e-12f), -1.f), 1.f);
    float ele = acosf(ce);

    // radial pair: closed form of ref's half-bin boundary clamps
    float vr = r * 2.5f - 0.5f;
    int jr; float wr0, wr1;
    if (vr < 0.f)        { jr = 0; wr0 = 1.f; wr1 = 0.f; }
    else if (vr >= 4.f)  { jr = 3; wr0 = 0.f; wr1 = 5.f - vr; }
    else { jr = (int)vr; float f = vr - (float)jr; wr0 = 1.f - f; wr1 = f; }

    // azimuth pair: circular; slot sa covers bins (sa, sa+1 mod 30)
    float va = azi * (float)(AZI_N / 6.283185307179586) - 0.5f;
    float fj = floorf(va);
    int   j  = (int)fj;                 // in [-1, 29]
    float fa = va - fj;
    int sa = (j < 0) ? (AZI_N - 1) : j;
    float wa0 = 1.f - fa, wa1 = fa;

    // elevation pair: both-end half-bin clamps
    float ve = ele * (float)(ELE_N / 3.141592653589793) - 0.5f;
    int ke; float we0, we1;
    if (ve < 0.f)         { ke = 0;  we0 = 1.f; we1 = 0.f; }
    else if (ve >= 14.f)  { ke = 13; we0 = 0.f; we1 = 1.f; }
    else { ke = (int)ve; float f = ve - (float)ke; we0 = 1.f - f; we1 = f; }

    float p00 = wa0 * we0, p01 = wa0 * we1;
    float p10 = wa1 * we0, p11 = wa1 * we1;

    int s0 = ((b * RAD_N + jr) * AZI_N + sa) * KSL + ke;
    if (wr0 != 0.f)
        red_add4(&g_slots[s0], wr0 * p00, wr0 * p01, wr0 * p10, wr0 * p11);
    if (wr1 != 0.f)
        red_add4(&g_slots[s0 + PLANE_SLOTS], wr1 * p00, wr1 * p01, wr1 * p10, wr1 * p11);
}

__global__ void __launch_bounds__(NTHR, 6) fused_kernel(const float* __restrict__ pts,
                                                        float* __restrict__ out) {
    int gtid = blockIdx.x * NTHR + threadIdx.x;

    // ---- Phase 1: scatter, 2 points per iteration via 3x float2 loads ----
    const float2* p2 = (const float2*)pts;
    for (int g = gtid; g < NGRP2; g += NT) {
        float2 v0 = __ldg(p2 + 3 * g);
        float2 v1 = __ldg(p2 + 3 * g + 1);
        float2 v2 = __ldg(p2 + 3 * g + 2);
        int b = (2 * g) >> 16;            // both points share batch (NP even)
        scatter_point(v0.x, v0.y, v1.x, b);
        scatter_point(v1.y, v2.x, v2.y, b);
    }

    // ---- Grid barrier: atomic arrival, LOAD-based polling (no L2-atomic
    //      contention — ld.volatile is served in parallel by the LTS) ----
    __threadfence();          // make this block's red ops globally visible
    __syncthreads();
    if (threadIdx.x == 0) {
        volatile unsigned* genp = &g_bar_gen;
        unsigned old = *genp;             // read BEFORE arriving (else deadlock)
        unsigned t   = atomicAdd(&g_bar_count, 1u);
        if (t == NBLK - 1) {
            atomicExch(&g_bar_count, 0u); // self-reset for next replay
            __threadfence();
            atomicAdd(&g_bar_gen, 1u);    // release
        } else {
            while (*genp == old) { __nanosleep(32); }
        }
        __threadfence();                  // acquire: other blocks' reds visible
    }
    __syncthreads();

    // ---- Phase 2: blocks 0..79 fold one (b,r) plane each, re-zeroing slots ----
    if (blockIdx.x < NPLANE) {
        __shared__ float4 s[PLANE_SLOTS];
        int plane = blockIdx.x;
        int tid = threadIdx.x;

        float4* gp = g_slots + plane * PLANE_SLOTS;
        for (int i = tid; i < PLANE_SLOTS; i += NTHR) {
            float4 v = __ldcg(&gp[i]);    // bypass L1: red updates L2 only
            s[i] = v;
            __stcg(&gp[i], make_float4(0.f, 0.f, 0.f, 0.f));  // restore invariant
        }
        __syncthreads();

        for (int i = tid; i < PLANE_OUTS; i += NTHR) {
            int e   = i % ELE_N;
            int a   = i / ELE_N;
            int am1 = (a == 0) ? (AZI_N - 1) : (a - 1);

            float v = 0.f;
            if (e < KSL) {
                v += s[a   * KSL + e].x;
                v += s[am1 * KSL + e].z;
            }
            if (e > 0) {
                v += s[a   * KSL + e - 1].y;
                v += s[am1 * KSL + e - 1].w;
            }
            out[plane * PLANE_OUTS + i] = v;
        }
    }
}

extern "C" void kernel_launch(void* const* d_in, const int* in_sizes, int n_in,
                              void* d_out, int out_size) {
    const float* pts = (const float*)d_in[0];
    float* out = (float*)d_out;
    fused_kernel<<<NBLK, NTHR>>>(pts, out);
}

// round 11
// speedup vs baseline: 1.2301x; 1.1252x over previous
#include <cuda_runtime.h>

#define NB     16
#define NP     65536
#define NPTS   (NB * NP)                            // 1048576 points
#define RAD_N  5
#define AZI_N  30
#define ELE_N  15
#define KSL    (ELE_N - 1)                          // 14 ele pair-slots
#define PLANE_SLOTS (AZI_N * KSL)                   // 420 slots per (b,r) plane
#define PLANE_OUTS  (AZI_N * ELE_N)                 // 450 out bins per plane
#define NPLANE (NB * RAD_N)                         // 80 planes
#define NSLOT  (NPLANE * PLANE_SLOTS)               // 33600 float4 2x2-slots

// 2x2 pair-slot histogram: slot[b][r][a][k] (a circular, k=0..13) holds
// contributions to bins (a,k),(a,k+1),(a+1%30,k),(a+1%30,k+1) in (.x,.y,.z,.w).
// INVARIANT: all-zero at entry of kernel_launch (zero-init at module load;
// fold_reset_kernel restores zeros after reading each replay).
__device__ float4 g_slots[NSLOT];

__device__ __forceinline__ void red_add4(float4* a, float x, float y, float z, float w) {
    asm volatile("red.global.add.v4.f32 [%0], {%1, %2, %3, %4};"
                 :: "l"(a), "f"(x), "f"(y), "f"(z), "f"(w) : "memory");
}

__device__ __forceinline__ void scatter_point(float x, float y, float z, int b) {
    float r = sqrtf(x * x + y * y + z * z);
    if (r > 2.0f) return;   // reference culls r > DES_R

    float azi = atan2f(y, x);
    if (azi < 0.f) azi += 6.28318530717958647692f;
    float ce  = fminf(fmaxf(z / fmaxf(r, 1e-12f), -1.f), 1.f);
    float ele = acosf(ce);

    // radial pair: closed form of ref's half-bin boundary clamps
    float vr = r * 2.5f - 0.5f;
    int jr; float wr0, wr1;
    if (vr < 0.f)        { jr = 0; wr0 = 1.f; wr1 = 0.f; }
    else if (vr >= 4.f)  { jr = 3; wr0 = 0.f; wr1 = 5.f - vr; }
    else { jr = (int)vr; float f = vr - (float)jr; wr0 = 1.f - f; wr1 = f; }

    // azimuth pair: circular; slot sa covers bins (sa, sa+1 mod 30)
    float va = azi * (float)(AZI_N / 6.283185307179586) - 0.5f;
    float fj = floorf(va);
    int   j  = (int)fj;                 // in [-1, 29]
    float fa = va - fj;
    int sa = (j < 0) ? (AZI_N - 1) : j;
    float wa0 = 1.f - fa, wa1 = fa;

    // elevation pair: both-end half-bin clamps
    float ve = ele * (float)(ELE_N / 3.141592653589793) - 0.5f;
    int ke; float we0, we1;
    if (ve < 0.f)         { ke = 0;  we0 = 1.f; we1 = 0.f; }
    else if (ve >= 14.f)  { ke = 13; we0 = 0.f; we1 = 1.f; }
    else { ke = (int)ve; float f = ve - (float)ke; we0 = 1.f - f; we1 = f; }

    float p00 = wa0 * we0, p01 = wa0 * we1;
    float p10 = wa1 * we0, p11 = wa1 * we1;

    int s0 = ((b * RAD_N + jr) * AZI_N + sa) * KSL + ke;
    if (wr0 != 0.f)
        red_add4(&g_slots[s0], wr0 * p00, wr0 * p01, wr0 * p10, wr0 * p11);
    if (wr1 != 0.f)
        red_add4(&g_slots[s0 + PLANE_SLOTS], wr1 * p00, wr1 * p01, wr1 * p10, wr1 * p11);
}

// 4 points per thread via 3x float4 loads: full coalescing + 4-way independent
// ILP to cover DRAM/MUFU latency. 262144 threads = 1024 blocks.
__global__ void __launch_bounds__(256) vox_kernel(const float* __restrict__ pts) {
    // PDL: release dependent (fold) launch immediately; it parks on
    // griddepcontrol.wait until this grid completes.
    asm volatile("griddepcontrol.launch_dependents;");

    int g = blockIdx.x * 256 + threadIdx.x;     // exact multiple, no guard
    const float4* p4 = (const float4*)pts;
    float4 A = __ldg(p4 + 3 * g);
    float4 B = __ldg(p4 + 3 * g + 1);
    float4 C = __ldg(p4 + 3 * g + 2);
    int b = (g * 4) >> 16;                      // 4 pts share batch (NP%4==0)

    scatter_point(A.x, A.y, A.z, b);
    scatter_point(A.w, B.x, B.y, b);
    scatter_point(B.z, B.w, C.x, b);
    scatter_point(C.y, C.z, C.w, b);
}

// One block per (b,r) plane. Stages the plane's 420 slots in smem
// (L1-bypassed: red.global updates L2 only), re-zeros them (restoring the
// invariant for the next replay), then folds 450 output bins from smem.
__global__ void __launch_bounds__(512) fold_reset_kernel(float* __restrict__ out) {
    // PDL: wait for vox grid completion (also orders its memory ops before
    // our reads). Launch/prologue overhead overlaps with vox execution.
    asm volatile("griddepcontrol.wait;");

    __shared__ float4 s[PLANE_SLOTS];
    int plane = blockIdx.x;              // rb = b*5 + r
    int tid = threadIdx.x;

    float4* gp = g_slots + plane * PLANE_SLOTS;
    if (tid < PLANE_SLOTS) {
        float4 v = __ldcg(&gp[tid]);
        s[tid] = v;
        __stcg(&gp[tid], make_float4(0.f, 0.f, 0.f, 0.f));
    }
    __syncthreads();

    if (tid < PLANE_OUTS) {
        int e   = tid % ELE_N;
        int a   = tid / ELE_N;
        int am1 = (a == 0) ? (AZI_N - 1) : (a - 1);

        float v = 0.f;
        if (e < KSL) {
            v += s[a   * KSL + e].x;
            v += s[am1 * KSL + e].z;
        }
        if (e > 0) {
            v += s[a   * KSL + e - 1].y;
            v += s[am1 * KSL + e - 1].w;
        }
        out[plane * PLANE_OUTS + tid] = v;
    }
}

extern "C" void kernel_launch(void* const* d_in, const int* in_sizes, int n_in,
                              void* d_out, int out_size) {
    const float* pts = (const float*)d_in[0];
    float* out = (float*)d_out;

    vox_kernel<<<NPTS / 4 / 256, 256>>>(pts);

    // Launch fold with Programmatic Stream Serialization (PDL).
    cudaLaunchConfig_t cfg = {};
    cfg.gridDim  = dim3(NPLANE, 1, 1);
    cfg.blockDim = dim3(512, 1, 1);
    cfg.dynamicSmemBytes = 0;
    cfg.stream = 0;   // legacy default stream (same as <<<>>>; captured fine)
    cudaLaunchAttribute at[1];
    at[0].id = cudaLaunchAttributeProgrammaticStreamSerialization;
    at[0].val.programmaticStreamSerializationAllowed = 1;
    cfg.attrs = at;
    cfg.numAttrs = 1;
    cudaLaunchKernelEx(&cfg, fold_reset_kernel, out);
}